// round 2
// baseline (speedup 1.0000x reference)
#include <cuda_runtime.h>
#include <float.h>

// Problem constants (fixed: B=4, M=1024, N=32768)
#define BB 4
#define MM 1024
#define NN 32768
#define NPAIRS (NN / 2)        // 16384 point-pairs per batch
#define NCHUNK 111             // chunks per batch; 111*4 = 444 blocks = 3 per SM (148 SMs)
#define PAIRS_PER_CHUNK 148    // ceil(16384/111); tail clamped (duplicates can't change min)
#define KT 8                   // keypoints per thread
#define NTHREADS 128           // 128 * 8 = 1024 = MM keypoints covered per block

typedef unsigned long long u64;

// Scratch (no cudaMalloc allowed)
__device__ float g_partial[BB * NCHUNK * MM];  // per-chunk min of (|p|^2 - 2 k.p)
__device__ float g_bsum[16];                   // per-block sums from reduce1

// ---- packed f32x2 helpers (Blackwell-only FFMA2 path) ----
__device__ __forceinline__ u64 fma2(u64 a, u64 b, u64 c) {
    u64 d; asm("fma.rn.f32x2 %0, %1, %2, %3;" : "=l"(d) : "l"(a), "l"(b), "l"(c));
    return d;
}
__device__ __forceinline__ u64 mul2(u64 a, u64 b) {
    u64 d; asm("mul.rn.f32x2 %0, %1, %2;" : "=l"(d) : "l"(a), "l"(b));
    return d;
}
__device__ __forceinline__ u64 dup2(float x) {
    u64 d; asm("mov.b64 %0, {%1, %1};" : "=l"(d) : "f"(x));
    return d;
}
__device__ __forceinline__ void unpack2(u64 v, float& lo, float& hi) {
    asm("mov.b64 {%0, %1}, %2;" : "=f"(lo), "=f"(hi) : "l"(v));
}

// --- Kernel 1: per (chunk, b) block: min over chunk points for all 1024 keypoints ---
// v = |p|^2 - 2 k.p   (then d2 = |k|^2 + min_v, computed in the reduce)
__global__ void __launch_bounds__(NTHREADS)
min_kernel(const float* __restrict__ kpt, const float* __restrict__ pc) {
    const int chunk = blockIdx.x;
    const int b     = blockIdx.y;
    const int t     = threadIdx.x;
    const int m0    = t * KT;

    // Per-thread keypoints, negated*2 and duplicated into both f32x2 halves (hoisted).
    const float* kb = kpt + (size_t)b * 3 * MM;
    u64 knx[KT], kny[KT], knz[KT];
    float mnl[KT], mnh[KT];
#pragma unroll
    for (int j = 0; j < KT; j++) {
        knx[j] = dup2(-2.0f * kb[m0 + j]);
        kny[j] = dup2(-2.0f * kb[MM + m0 + j]);
        knz[j] = dup2(-2.0f * kb[2 * MM + m0 + j]);
        mnl[j] = FLT_MAX;
        mnh[j] = FLT_MAX;
    }

    // Planar pc: aligned LDG.64 at (plane + 2q) gives the packed point-pair directly.
    const float* pcb = pc + (size_t)b * 3 * NN;
    const u64* __restrict__ pxp = (const u64*)pcb;
    const u64* __restrict__ pyp = (const u64*)(pcb + NN);
    const u64* __restrict__ pzp = (const u64*)(pcb + 2 * NN);

    const int q0 = chunk * PAIRS_PER_CHUNK;
#pragma unroll 2
    for (int i = 0; i < PAIRS_PER_CHUNK; i++) {
        int q = q0 + i;
        q = min(q, NPAIRS - 1);  // tail clamp: re-processing a real point is a no-op for min
        u64 x2 = pxp[q];
        u64 y2 = pyp[q];
        u64 z2 = pzp[q];
        u64 pp = fma2(z2, z2, fma2(y2, y2, mul2(x2, x2)));  // (|p0|^2, |p1|^2)
#pragma unroll
        for (int j = 0; j < KT; j++) {
            u64 v = fma2(knx[j], x2, fma2(kny[j], y2, fma2(knz[j], z2, pp)));
            float lo, hi;
            unpack2(v, lo, hi);
            mnl[j] = fminf(mnl[j], lo);
            mnh[j] = fminf(mnh[j], hi);
        }
    }

    // Combine halves, write 8 consecutive floats (two float4 stores).
    float* outp = g_partial + ((size_t)(b * NCHUNK + chunk)) * MM + m0;
    float4 o0, o1;
    o0.x = fminf(mnl[0], mnh[0]);
    o0.y = fminf(mnl[1], mnh[1]);
    o0.z = fminf(mnl[2], mnh[2]);
    o0.w = fminf(mnl[3], mnh[3]);
    o1.x = fminf(mnl[4], mnh[4]);
    o1.y = fminf(mnl[5], mnh[5]);
    o1.z = fminf(mnl[6], mnh[6]);
    o1.w = fminf(mnl[7], mnh[7]);
    ((float4*)outp)[0] = o0;
    ((float4*)outp)[1] = o1;
}

// --- Kernel 2: per (b,m) row: min over 111 chunks, d = sqrt(max(|k|^2 + v, 0)), partial sums ---
__global__ void __launch_bounds__(256)
reduce1_kernel(const float* __restrict__ kpt) {
    const int r = blockIdx.x * 256 + threadIdx.x;  // 16*256 = 4096 = BB*MM rows
    const int b = r / MM;
    const int m = r % MM;

    const float* p = g_partial + (size_t)b * NCHUNK * MM + m;
    float v = p[0];
#pragma unroll 4
    for (int c = 1; c < NCHUNK; c++) v = fminf(v, p[(size_t)c * MM]);

    const float* kb = kpt + (size_t)b * 3 * MM;
    float x = kb[m], y = kb[MM + m], z = kb[2 * MM + m];
    float d2 = fmaxf(v + (x * x + y * y + z * z), 0.0f);
    float d = sqrtf(d2);

    __shared__ float ss[256];
    ss[threadIdx.x] = d;
    __syncthreads();
#pragma unroll
    for (int s = 128; s; s >>= 1) {
        if (threadIdx.x < s) ss[threadIdx.x] += ss[threadIdx.x + s];
        __syncthreads();
    }
    if (threadIdx.x == 0) g_bsum[blockIdx.x] = ss[0];
}

// --- Kernel 3: final sum of 16 block sums -> mean ---
__global__ void reduce2_kernel(float* __restrict__ out) {
    float v = (threadIdx.x < 16) ? g_bsum[threadIdx.x] : 0.0f;
#pragma unroll
    for (int off = 16; off; off >>= 1) v += __shfl_xor_sync(0xffffffffu, v, off);
    if (threadIdx.x == 0) *out = v * (1.0f / (float)(BB * MM));
}

extern "C" void kernel_launch(void* const* d_in, const int* in_sizes, int n_in,
                              void* d_out, int out_size) {
    const float* keypoints = (const float*)d_in[0];  // [B,3,M]
    const float* pc        = (const float*)d_in[1];  // [B,3,N]
    float* out             = (float*)d_out;          // scalar

    (void)in_sizes; (void)n_in; (void)out_size;

    dim3 grid(NCHUNK, BB);
    min_kernel<<<grid, NTHREADS>>>(keypoints, pc);
    reduce1_kernel<<<16, 256>>>(keypoints);
    reduce2_kernel<<<1, 32>>>(out);
}

// round 3
// speedup vs baseline: 1.0429x; 1.0429x over previous
#include <cuda_runtime.h>
#include <float.h>

// Problem constants (fixed: B=4, M=1024, N=32768)
#define BB 4
#define MM 1024
#define NN 32768
#define NPAIRS (NN / 2)        // 16384 point-pairs per batch
#define NCHUNK 333             // chunks per batch; 333*4 = 1332 blocks = 9/SM (reg-limited)
#define PAIRS_PER_CHUNK 50     // ceil(16384/333); tail clamped (duplicate point is a min no-op)
#define KT 8                   // keypoints per thread
#define NTHREADS 128           // 128 * 8 = 1024 = MM keypoints covered per block
#define R1_BLOCKS 64

typedef unsigned long long u64;

// Scratch (no cudaMalloc allowed)
// Layout: [row = b*MM + m][chunk]  -> contiguous per row for a coalesced warp reduce.
__device__ float g_partial[BB * MM * NCHUNK];
__device__ float g_bsum[R1_BLOCKS];

// ---- packed f32x2 helpers (Blackwell FFMA2 path) ----
__device__ __forceinline__ u64 fma2(u64 a, u64 b, u64 c) {
    u64 d; asm("fma.rn.f32x2 %0, %1, %2, %3;" : "=l"(d) : "l"(a), "l"(b), "l"(c));
    return d;
}
__device__ __forceinline__ u64 mul2(u64 a, u64 b) {
    u64 d; asm("mul.rn.f32x2 %0, %1, %2;" : "=l"(d) : "l"(a), "l"(b));
    return d;
}
__device__ __forceinline__ u64 dup2(float x) {
    u64 d; asm("mov.b64 %0, {%1, %1};" : "=l"(d) : "f"(x));
    return d;
}
__device__ __forceinline__ void unpack2(u64 v, float& lo, float& hi) {
    asm("mov.b64 {%0, %1}, %2;" : "=f"(lo), "=f"(hi) : "l"(v));
}

// --- Kernel 1: per (chunk, b) block: min over chunk points for all 1024 keypoints ---
// v = |p|^2 - 2 k.p   (then d2 = |k|^2 + min v, applied in the reduce)
__global__ void __launch_bounds__(NTHREADS)
min_kernel(const float* __restrict__ kpt, const float* __restrict__ pc) {
    const int chunk = blockIdx.x;
    const int b     = blockIdx.y;
    const int t     = threadIdx.x;
    const int m0    = t * KT;

    // Per-thread keypoints, scaled by -2 and duplicated into both f32x2 halves (hoisted).
    const float* kb = kpt + (size_t)b * 3 * MM;
    u64 knx[KT], kny[KT], knz[KT];
    float mnl[KT], mnh[KT];
#pragma unroll
    for (int j = 0; j < KT; j++) {
        knx[j] = dup2(-2.0f * kb[m0 + j]);
        kny[j] = dup2(-2.0f * kb[MM + m0 + j]);
        knz[j] = dup2(-2.0f * kb[2 * MM + m0 + j]);
        mnl[j] = FLT_MAX;
        mnh[j] = FLT_MAX;
    }

    // Planar pc: aligned LDG.64 at (plane + 2q) gives the packed point-pair directly.
    const float* pcb = pc + (size_t)b * 3 * NN;
    const u64* __restrict__ pxp = (const u64*)pcb;
    const u64* __restrict__ pyp = (const u64*)(pcb + NN);
    const u64* __restrict__ pzp = (const u64*)(pcb + 2 * NN);

    const int q0 = chunk * PAIRS_PER_CHUNK;
#pragma unroll 2
    for (int i = 0; i < PAIRS_PER_CHUNK; i++) {
        int q = q0 + i;
        q = min(q, NPAIRS - 1);  // tail clamp: re-processing a real point can't change a min
        u64 x2 = pxp[q];
        u64 y2 = pyp[q];
        u64 z2 = pzp[q];
        u64 pp = fma2(z2, z2, fma2(y2, y2, mul2(x2, x2)));  // (|p0|^2, |p1|^2)
#pragma unroll
        for (int j = 0; j < KT; j++) {
            u64 v = fma2(knx[j], x2, fma2(kny[j], y2, fma2(knz[j], z2, pp)));
            float lo, hi;
            unpack2(v, lo, hi);  // register-pair aliasing: no real MOVs
            mnl[j] = fminf(mnl[j], lo);
            mnh[j] = fminf(mnh[j], hi);
        }
    }

    // Transposed scatter: row-contiguous layout for the reduce. 8 scalar STG, no syncs.
#pragma unroll
    for (int j = 0; j < KT; j++) {
        size_t row = (size_t)b * MM + m0 + j;
        g_partial[row * NCHUNK + chunk] = fminf(mnl[j], mnh[j]);
    }
}

// --- Kernel 2: one warp per row: min over NCHUNK, d = sqrt(max(|k|^2+v,0)), partial sums ---
__global__ void __launch_bounds__(256)
reduce1_kernel(const float* __restrict__ kpt) {
    const int warp = threadIdx.x >> 5, lane = threadIdx.x & 31;
    float sum = 0.0f;

#pragma unroll
    for (int rr = 0; rr < 8; rr++) {          // 64 blocks * 8 warps * 8 rows = 4096 rows
        int row = (blockIdx.x * 8 + warp) * 8 + rr;
        const float* p = g_partial + (size_t)row * NCHUNK;
        float v = FLT_MAX;
        for (int c = lane; c < NCHUNK; c += 32) v = fminf(v, p[c]);  // coalesced
#pragma unroll
        for (int off = 16; off; off >>= 1)
            v = fminf(v, __shfl_xor_sync(0xffffffffu, v, off));
        if (lane == 0) {
            int b = row >> 10, m = row & (MM - 1);
            const float* kb = kpt + (size_t)b * 3 * MM;
            float x = kb[m], y = kb[MM + m], z = kb[2 * MM + m];
            float d2 = fmaxf(v + (x * x + y * y + z * z), 0.0f);
            sum += sqrtf(d2);
        }
    }

    __shared__ float ws[8];
    if (lane == 0) ws[warp] = sum;
    __syncthreads();
    if (threadIdx.x == 0) {
        float s = 0.0f;
#pragma unroll
        for (int w = 0; w < 8; w++) s += ws[w];
        g_bsum[blockIdx.x] = s;
    }
}

// --- Kernel 3: fold 64 block sums -> mean ---
__global__ void reduce2_kernel(float* __restrict__ out) {
    int lane = threadIdx.x;
    float v = g_bsum[lane] + g_bsum[lane + 32];
#pragma unroll
    for (int off = 16; off; off >>= 1) v += __shfl_xor_sync(0xffffffffu, v, off);
    if (lane == 0) *out = v * (1.0f / (float)(BB * MM));
}

extern "C" void kernel_launch(void* const* d_in, const int* in_sizes, int n_in,
                              void* d_out, int out_size) {
    const float* keypoints = (const float*)d_in[0];  // [B,3,M]
    const float* pc        = (const float*)d_in[1];  // [B,3,N]
    float* out             = (float*)d_out;          // scalar

    (void)in_sizes; (void)n_in; (void)out_size;

    dim3 grid(NCHUNK, BB);
    min_kernel<<<grid, NTHREADS>>>(keypoints, pc);
    reduce1_kernel<<<R1_BLOCKS, 256>>>(keypoints);
    reduce2_kernel<<<1, 32>>>(out);
}

// round 4
// speedup vs baseline: 1.1674x; 1.1193x over previous
#include <cuda_runtime.h>
#include <float.h>

// Problem constants (fixed: B=4, M=1024, N=32768)
#define BB 4
#define MM 1024
#define NN 32768
#define NPAIRS (NN / 2)        // 16384 point-pairs per batch
#define NCHUNK 148             // chunks per batch; 148*4 = 592 blocks = exactly 4/SM, 1 wave
#define TILE 111               // ceil(16384/148); tail clamped at copy time
#define KT 8                   // keypoints per thread
#define NTHREADS 128           // 128 * 8 = 1024 = all keypoints per block
#define R1_BLOCKS 32

typedef unsigned long long u64;

// Scratch (no cudaMalloc allowed). Chunk-major: [chunk][b*MM+m] -> coalesced stores
// in min_kernel AND coalesced loads in reduce1.
__device__ float g_partial[NCHUNK * BB * MM];
__device__ float g_bsum[R1_BLOCKS];

// ---- packed f32x2 helpers (Blackwell FFMA2 path) ----
__device__ __forceinline__ u64 fma2(u64 a, u64 b, u64 c) {
    u64 d; asm("fma.rn.f32x2 %0, %1, %2, %3;" : "=l"(d) : "l"(a), "l"(b), "l"(c));
    return d;
}
__device__ __forceinline__ u64 mul2(u64 a, u64 b) {
    u64 d; asm("mul.rn.f32x2 %0, %1, %2;" : "=l"(d) : "l"(a), "l"(b));
    return d;
}
__device__ __forceinline__ u64 dup2(float x) {
    u64 d; asm("mov.b64 %0, {%1, %1};" : "=l"(d) : "f"(x));
    return d;
}
__device__ __forceinline__ void unpack2(u64 v, float& lo, float& hi) {
    asm("mov.b64 {%0, %1}, %2;" : "=f"(lo), "=f"(hi) : "l"(v));
}

// --- Kernel 1: per (chunk, b) block: min over chunk's points for all 1024 keypoints.
// v = |p|^2 - 2 k.p  (d2 = |k|^2 + min v applied in the reduce).
// Points staged in smem once per block; |p|^2 precomputed once (not per thread).
__global__ void __launch_bounds__(NTHREADS, 4)
min_kernel(const float* __restrict__ kpt, const float* __restrict__ pc) {
    const int chunk = blockIdx.x;
    const int b     = blockIdx.y;
    const int t     = threadIdx.x;
    const int m0    = t * KT;

    // smem: per pair i: s_pts[2i]={x2,y2}, s_pts[2i+1]={z2,pp}  (two LDS.128 per iter)
    __shared__ ulonglong2 s_pts[2 * TILE];

    // Copy phase: stage this chunk's point-pairs + packed |p|^2.
    if (t < TILE) {
        int q = min(chunk * TILE + t, NPAIRS - 1);  // tail clamp: dup pair is a min no-op
        const float* pcb = pc + (size_t)b * 3 * NN;
        u64 x2 = ((const u64*)pcb)[q];
        u64 y2 = ((const u64*)(pcb + NN))[q];
        u64 z2 = ((const u64*)(pcb + 2 * NN))[q];
        u64 pp = fma2(z2, z2, fma2(y2, y2, mul2(x2, x2)));  // (|p0|^2, |p1|^2)
        ulonglong2 a, c;
        a.x = x2; a.y = y2;
        c.x = z2; c.y = pp;
        s_pts[2 * t]     = a;
        s_pts[2 * t + 1] = c;
    }

    // Per-thread keypoints, scaled by -2, duplicated into both f32x2 halves (hoisted).
    const float* kb = kpt + (size_t)b * 3 * MM;
    u64 knx[KT], kny[KT], knz[KT];
    float mnl[KT], mnh[KT];
#pragma unroll
    for (int j = 0; j < KT; j++) {
        knx[j] = dup2(-2.0f * kb[m0 + j]);
        kny[j] = dup2(-2.0f * kb[MM + m0 + j]);
        knz[j] = dup2(-2.0f * kb[2 * MM + m0 + j]);
        mnl[j] = FLT_MAX;
        mnh[j] = FLT_MAX;
    }
    __syncthreads();

    // Main loop: pure compute against smem (broadcast LDS, conflict-free).
#pragma unroll 3
    for (int i = 0; i < TILE; i++) {
        ulonglong2 a = s_pts[2 * i];      // (x2, y2)
        ulonglong2 c = s_pts[2 * i + 1];  // (z2, pp)
#pragma unroll
        for (int j = 0; j < KT; j++) {
            u64 v = fma2(knx[j], a.x, fma2(kny[j], a.y, fma2(knz[j], c.x, c.y)));
            float lo, hi;
            unpack2(v, lo, hi);  // register-pair aliasing, no real MOVs
            mnl[j] = fminf(mnl[j], lo);
            mnh[j] = fminf(mnh[j], hi);
        }
    }

    // Coalesced store: 8 consecutive floats per thread (two STG.128).
    float* outp = g_partial + (size_t)chunk * (BB * MM) + b * MM + m0;
    float4 o0, o1;
    o0.x = fminf(mnl[0], mnh[0]);
    o0.y = fminf(mnl[1], mnh[1]);
    o0.z = fminf(mnl[2], mnh[2]);
    o0.w = fminf(mnl[3], mnh[3]);
    o1.x = fminf(mnl[4], mnh[4]);
    o1.y = fminf(mnl[5], mnh[5]);
    o1.z = fminf(mnl[6], mnh[6]);
    o1.w = fminf(mnl[7], mnh[7]);
    ((float4*)outp)[0] = o0;
    ((float4*)outp)[1] = o1;
}

// --- Kernel 2: per row (b,m): min over NCHUNK chunk-partials (coalesced, chunk-major),
// d = sqrt(max(|k|^2 + v, 0)), then block partial sums.
__global__ void __launch_bounds__(128)
reduce1_kernel(const float* __restrict__ kpt) {
    const int r = blockIdx.x * 128 + threadIdx.x;  // 32*128 = 4096 rows
    const float* p = g_partial + r;
    float v = FLT_MAX;
#pragma unroll 4
    for (int c = 0; c < NCHUNK; c++) v = fminf(v, p[(size_t)c * (BB * MM)]);

    const int b = r >> 10, m = r & (MM - 1);
    const float* kb = kpt + (size_t)b * 3 * MM;
    float x = kb[m], y = kb[MM + m], z = kb[2 * MM + m];
    float d = sqrtf(fmaxf(v + (x * x + y * y + z * z), 0.0f));

    __shared__ float ss[128];
    ss[threadIdx.x] = d;
    __syncthreads();
#pragma unroll
    for (int s = 64; s; s >>= 1) {
        if (threadIdx.x < s) ss[threadIdx.x] += ss[threadIdx.x + s];
        __syncthreads();
    }
    if (threadIdx.x == 0) g_bsum[blockIdx.x] = ss[0];
}

// --- Kernel 3: fold 32 block sums -> mean ---
__global__ void reduce2_kernel(float* __restrict__ out) {
    float v = g_bsum[threadIdx.x];
#pragma unroll
    for (int off = 16; off; off >>= 1) v += __shfl_xor_sync(0xffffffffu, v, off);
    if (threadIdx.x == 0) *out = v * (1.0f / (float)(BB * MM));
}

extern "C" void kernel_launch(void* const* d_in, const int* in_sizes, int n_in,
                              void* d_out, int out_size) {
    const float* keypoints = (const float*)d_in[0];  // [B,3,M]
    const float* pc        = (const float*)d_in[1];  // [B,3,N]
    float* out             = (float*)d_out;          // scalar

    (void)in_sizes; (void)n_in; (void)out_size;

    dim3 grid(NCHUNK, BB);
    min_kernel<<<grid, NTHREADS>>>(keypoints, pc);
    reduce1_kernel<<<R1_BLOCKS, 128>>>(keypoints);
    reduce2_kernel<<<1, 32>>>(out);
}